// round 10
// baseline (speedup 1.0000x reference)
#include <cuda_runtime.h>
#include <cuda_fp16.h>
#include <cstdint>

// ---------------- problem constants ----------------
#define SB   4
#define SS   2048
#define SEQ  2046
#define NH   12
#define ND   64
#define ROWSTRIDE (NH*ND)        // 768 elems between consecutive l in v
#define NV   (SB*SS*NH*ND)       // 6291456 elements of v

// ---------------- GEMM tiling (R7/R9-proven) ----------------
#define TM    64                 // j rows per CTA
#define TN    128                // c cols per CTA
#define KC    32                 // l per chunk
#define NCHUNK (SS / KC)         // 64
#define THREADS 256

#define A_STR  40                // halves per j row (32 k + 8 pad)
#define B_STR  136               // halves per k row (128 c + 8 pad)
#define A_BYTES (TM * A_STR * 2)          // 5120
#define B_BYTES (KC * B_STR * 2)          // 8704
#define DYN_BYTES (2*A_BYTES + 2*B_BYTES) // 27648

// fp16 copy of v (device-global scratch)
__device__ __half vt_h[NV];

__device__ __forceinline__ uint32_t smem_u32(const void* p) {
    uint32_t a;
    asm("{ .reg .u64 t; cvta.to.shared.u64 t, %1; cvt.u32.u64 %0, t; }"
        : "=r"(a) : "l"(p));
    return a;
}
__device__ __forceinline__ void cp_async16(uint32_t dst, const void* src) {
    asm volatile("cp.async.ca.shared.global [%0], [%1], 16;"
                 :: "r"(dst), "l"(src) : "memory");
}
#define CP_COMMIT() asm volatile("cp.async.commit_group;" ::: "memory")
#define CP_WAIT0()  asm volatile("cp.async.wait_group 0;" ::: "memory")

__device__ __forceinline__ void ldsm_x4(uint32_t* r, uint32_t addr) {
    asm volatile("ldmatrix.sync.aligned.m8n8.x4.shared.b16 {%0,%1,%2,%3}, [%4];"
                 : "=r"(r[0]), "=r"(r[1]), "=r"(r[2]), "=r"(r[3]) : "r"(addr));
}
__device__ __forceinline__ void ldsm_x4_t(uint32_t* r, uint32_t addr) {
    asm volatile("ldmatrix.sync.aligned.m8n8.x4.trans.shared.b16 {%0,%1,%2,%3}, [%4];"
                 : "=r"(r[0]), "=r"(r[1]), "=r"(r[2]), "=r"(r[3]) : "r"(addr));
}
// fp16-accumulate variant: D,C are 2 regs (4 halves). First k-step seeds with
// zero C; second accumulates in fp16. Promoted to fp32 each chunk.
__device__ __forceinline__ void mma_f16acc_seed(uint32_t* d, const uint32_t* a,
                                                const uint32_t* b, uint32_t z) {
    asm volatile(
        "mma.sync.aligned.m16n8k16.row.col.f16.f16.f16.f16 "
        "{%0,%1}, {%2,%3,%4,%5}, {%6,%7}, {%8,%8};"
        : "=r"(d[0]), "=r"(d[1])
        : "r"(a[0]), "r"(a[1]), "r"(a[2]), "r"(a[3]), "r"(b[0]), "r"(b[1]),
          "r"(z));
}
__device__ __forceinline__ void mma_f16acc(uint32_t* d, const uint32_t* a,
                                           const uint32_t* b) {
    asm volatile(
        "mma.sync.aligned.m16n8k16.row.col.f16.f16.f16.f16 "
        "{%0,%1}, {%2,%3,%4,%5}, {%6,%7}, {%0,%1};"
        : "+r"(d[0]), "+r"(d[1])
        : "r"(a[0]), "r"(a[1]), "r"(a[2]), "r"(a[3]), "r"(b[0]), "r"(b[1]));
}

// ---------------------------------------------------------------------------
// convert v (fp32) -> vt_h (fp16); 8 elements per thread
// ---------------------------------------------------------------------------
__global__ __launch_bounds__(256) void cvt_kernel(const float* __restrict__ v) {
    int i = (blockIdx.x * 256 + threadIdx.x) * 8;
    float4 x0 = *(const float4*)(v + i);
    float4 x1 = *(const float4*)(v + i + 4);
    __half2 h[4];
    h[0] = __floats2half2_rn(x0.x, x0.y);
    h[1] = __floats2half2_rn(x0.z, x0.w);
    h[2] = __floats2half2_rn(x1.x, x1.y);
    h[3] = __floats2half2_rn(x1.z, x1.w);
    *(uint4*)(vt_h + i) = *(uint4*)h;
}

// ---------------------------------------------------------------------------
// pbv[n,j,h,d] = sum_l w[h,|l-j|] * v[n,l,h,d] as per-head Toeplitz GEMM.
// grid (32 j-tiles, 2 c-halves, 12 heads); CTA 64x128, 8 warps 32x32.
// fp16 accumulation within each KC=32 chunk, promoted to fp32 per chunk.
// ---------------------------------------------------------------------------
__global__ __launch_bounds__(THREADS, 3) void pbv_mma(const float* __restrict__ w,
                                                      float* __restrict__ out) {
    __shared__ __half wsh[SS];                  // 4 KB fp16 w row
    extern __shared__ char dyn[];               // A0 | A1 | B0 | B1

    const int t    = threadIdx.x;
    const int wid  = t >> 5, lane = t & 31;
    const int g    = lane >> 2, t4 = lane & 3;
    const int wm   = wid >> 2;                  // 0..1 -> 32-row slab
    const int wn   = wid & 3;                   // 0..3 -> 32-col slab
    const int l15  = lane & 15, lhi = lane >> 4;

    const int jt = blockIdx.x, ch = blockIdx.y, h = blockIdx.z;
    const int j0 = jt * TM;
    const int c0 = ch * TN;

    {
        const float* wrow = w + (size_t)h * SS;
        for (int i = t; i < SS; i += THREADS) wsh[i] = __float2half_rn(wrow[i]);
    }
    __syncthreads();

    const __half* vtb = vt_h + h * ND;          // + (n*SS + l)*ROWSTRIDE + d
    const uint32_t sb = smem_u32(dyn);

    const int skp = t & 15;                     // half2 pair within k row
    const int sj  = t >> 4;                     // j row 0..15 (+16*i)

    // ---- stage chunk `c` into buffer c&1
    auto stage = [&](int c) {
        const int k0 = c * KC;
        __half2* Ab = (__half2*)(dyn + (c & 1) * A_BYTES);
        const int l0 = k0 + 2 * skp;
        if (c != 0 && c != NCHUNK - 1) {        // fast path: all l valid
#pragma unroll
            for (int i = 0; i < 4; i++) {
                int jg = j0 + sj + 16 * i;
                int d0 = l0 - jg;     int a0i = d0 < 0 ? -d0 : d0;
                int d1 = d0 + 1;      int a1i = d1 < 0 ? -d1 : d1;
                Ab[(sj + 16 * i) * (A_STR / 2) + skp] =
                    __halves2half2(wsh[a0i], wsh[a1i]);
            }
        } else {                                 // edge chunks: l=0 / l=2047
#pragma unroll
            for (int i = 0; i < 4; i++) {
                int jg = j0 + sj + 16 * i;
                int d0 = l0 - jg;     int a0i = d0 < 0 ? -d0 : d0;
                int d1 = d0 + 1;      int a1i = d1 < 0 ? -d1 : d1;
                __half v0 = (l0 >= 1     && l0     <= SEQ) ? wsh[a0i] : __half(0.f);
                __half v1 = (l0 + 1 >= 1 && l0 + 1 <= SEQ) ? wsh[a1i] : __half(0.f);
                Ab[(sj + 16 * i) * (A_STR / 2) + skp] = __halves2half2(v0, v1);
            }
        }
        const uint32_t Bbase = sb + 2 * A_BYTES + (c & 1) * B_BYTES;
#pragma unroll
        for (int q = 0; q < 2; q++) {
            int fi = t + q * THREADS;           // 0..511, 16B slots
            int k  = fi >> 4, c8 = fi & 15;
            int cc = c0 + c8 * 8;
            int n  = cc >> 6, d = cc & 63;
            const __half* src = vtb + ((size_t)n * SS + (k0 + k)) * ROWSTRIDE + d;
            cp_async16(Bbase + (uint32_t)(k * B_STR + c8 * 8) * 2, src);
        }
        CP_COMMIT();
    };

    float acc[2][4][4];
#pragma unroll
    for (int mi = 0; mi < 2; mi++)
#pragma unroll
        for (int ni = 0; ni < 4; ni++)
#pragma unroll
            for (int r = 0; r < 4; r++) acc[mi][ni][r] = 0.f;

    const uint32_t aRow = (uint32_t)(wm * 32 + l15);       // + mi*16
    const uint32_t aKof = (uint32_t)(lhi * 8);             // + ks*16
    const uint32_t bRow = (uint32_t)l15;                   // + ks*16
    const uint32_t bCol = (uint32_t)(wn * 32 + lhi * 8);   // + ni2*16

    stage(0);

    for (int c = 0; c < NCHUNK; c++) {
        CP_WAIT0();
        __syncthreads();
        if (c + 1 < NCHUNK) stage(c + 1);

        const uint32_t Ao = sb + (c & 1) * A_BYTES;
        const uint32_t Bo = sb + 2 * A_BYTES + (c & 1) * B_BYTES;

        uint32_t hacc[2][4][2];                 // fp16x2 chunk accumulators

#pragma unroll
        for (int ks = 0; ks < 2; ks++) {
            uint32_t a[2][4], b[4][2];
#pragma unroll
            for (int mi = 0; mi < 2; mi++)
                ldsm_x4(a[mi], Ao + ((aRow + mi * 16) * A_STR + aKof + ks * 16) * 2);
#pragma unroll
            for (int ni2 = 0; ni2 < 2; ni2++) {
                uint32_t r[4];
                ldsm_x4_t(r, Bo + ((bRow + ks * 16) * B_STR + bCol + ni2 * 16) * 2);
                b[2 * ni2][0] = r[0];      b[2 * ni2][1] = r[1];
                b[2 * ni2 + 1][0] = r[2];  b[2 * ni2 + 1][1] = r[3];
            }
            if (ks == 0) {
#pragma unroll
                for (int mi = 0; mi < 2; mi++)
#pragma unroll
                    for (int ni = 0; ni < 4; ni++)
                        mma_f16acc_seed(hacc[mi][ni], a[mi], b[ni], 0u);
            } else {
#pragma unroll
                for (int mi = 0; mi < 2; mi++)
#pragma unroll
                    for (int ni = 0; ni < 4; ni++)
                        mma_f16acc(hacc[mi][ni], a[mi], b[ni]);
            }
        }
        // promote chunk sums into fp32 master accumulators
#pragma unroll
        for (int mi = 0; mi < 2; mi++)
#pragma unroll
            for (int ni = 0; ni < 4; ni++) {
                float2 lo = __half22float2(*(__half2*)&hacc[mi][ni][0]);
                float2 hi = __half22float2(*(__half2*)&hacc[mi][ni][1]);
                acc[mi][ni][0] += lo.x;  acc[mi][ni][1] += lo.y;
                acc[mi][ni][2] += hi.x;  acc[mi][ni][3] += hi.y;
            }
    }

    // ---- epilogue: acc -> out[n, j, h, d]
#pragma unroll
    for (int mi = 0; mi < 2; mi++) {
        const int r0 = j0 + wm * 32 + mi * 16 + g;
#pragma unroll
        for (int ni = 0; ni < 4; ni++) {
            const int cc = c0 + wn * 32 + ni * 8 + 2 * t4;
            const int n = cc >> 6, d = cc & 63;
            float* o = out + (((size_t)n * SS) * NH + h) * ND + d;
            if (r0 >= 1 && r0 <= SEQ) {
                float2 s = make_float2(acc[mi][ni][0], acc[mi][ni][1]);
                *(float2*)(o + (size_t)r0 * NH * ND) = s;
            }
            const int r1 = r0 + 8;
            if (r1 >= 1 && r1 <= SEQ) {
                float2 s = make_float2(acc[mi][ni][2], acc[mi][ni][3]);
                *(float2*)(o + (size_t)r1 * NH * ND) = s;
            }
        }
    }
}

// ---------------------------------------------------------------------------
// blocks 0..11: z_pb scan per head; blocks 12..17: zero pbv border rows
// ---------------------------------------------------------------------------
__global__ __launch_bounds__(1024) void zb_kernel(const float* __restrict__ w,
                                                  float* __restrict__ outz,
                                                  float* __restrict__ out) {
    const int b = blockIdx.x;
    if (b >= NH) {   // border: 6 blocks x 1024 cover 8 segs x 768
        int gidx = (b - NH) * 1024 + threadIdx.x;
        if (gidx < 8 * NH * ND) {
            int seg = gidx / (NH * ND);
            int off = gidx % (NH * ND);
            int n = seg >> 1;
            int j = (seg & 1) ? (SS - 1) : 0;
            out[((size_t)(n * SS + j) * NH * ND) + off] = 0.f;
        }
        return;
    }
    const int h = b;
    __shared__ float buf[2][SS];
    for (int i = threadIdx.x; i < SS; i += 1024)
        buf[0][i] = (i < SEQ) ? w[(size_t)h * SS + i] : 0.f;
    __syncthreads();
    int src = 0;
    for (int off = 1; off < SS; off <<= 1) {
        for (int i = threadIdx.x; i < SS; i += 1024) {
            float val = buf[src][i];
            if (i >= off) val += buf[src][i - off];
            buf[src ^ 1][i] = val;
        }
        src ^= 1;
        __syncthreads();
    }
    const float w0 = buf[src][0];
    for (int l = threadIdx.x; l < SS; l += 1024) {
        float zv = 0.f;
        if (l >= 1 && l <= SEQ)
            zv = buf[src][l - 1] + buf[src][SEQ - l] - w0;
        outz[(size_t)l * NH + h] = zv;
    }
}

// ---------------------------------------------------------------------------
extern "C" void kernel_launch(void* const* d_in, const int* in_sizes, int n_in,
                              void* d_out, int out_size) {
    const float* a0 = (const float*)d_in[0];
    const float* a1 = (const float*)d_in[1];
    const float* v = a0;
    const float* w = a1;
    if (n_in >= 2 && in_sizes[0] < in_sizes[1]) { v = a1; w = a0; }

    float* out  = (float*)d_out;
    float* outz = out + (size_t)SB * SS * NH * ND;

    static int configured = 0;
    if (!configured) {
        cudaFuncSetAttribute(pbv_mma, cudaFuncAttributeMaxDynamicSharedMemorySize,
                             DYN_BYTES);
        configured = 1;
    }

    cvt_kernel<<<NV / (256 * 8), 256>>>(v);
    dim3 grid(SS / TM, 256 / TN, NH);        // 32 x 2 x 12 = 768 CTAs
    pbv_mma<<<grid, THREADS, DYN_BYTES>>>(w, out);
    zb_kernel<<<NH + 6, 1024>>>(w, outz, out);
}

// round 12
// speedup vs baseline: 1.7816x; 1.7816x over previous
#include <cuda_runtime.h>
#include <cuda_fp16.h>
#include <cstdint>

// ---------------- problem constants ----------------
#define SB   4
#define SS   2048
#define SEQ  2046
#define NH   12
#define ND   64
#define ROWSTRIDE (NH*ND)        // 768 elems between consecutive l in v
#define NV   (SB*SS*NH*ND)       // 6291456 elements of v

// ---------------- GEMM tiling (R9-proven) ----------------
#define TM    64                 // j rows per CTA
#define TN    128                // c cols per CTA
#define KC    32                 // l per chunk
#define NCHUNK (SS / KC)         // 64
#define THREADS 256

#define A_STR  40                // halves per j row (32 k + 8 pad)
#define B_STR  136               // halves per k row (128 c + 8 pad)
#define A_BYTES (TM * A_STR * 2)          // 5120
#define B_BYTES (KC * B_STR * 2)          // 8704
#define DYN_BYTES (2*A_BYTES + 2*B_BYTES) // 27648

// fused front kernel grid split
#define CVT_BLOCKS 3072          // 3072 * 256 * 8 = NV
#define ZB_BLOCKS  17            // 12 scan + 5 border (5*1536 > 6144)

// fp16 copy of v (device-global scratch)
__device__ __half vt_h[NV];

__device__ __forceinline__ uint32_t smem_u32(const void* p) {
    uint32_t a;
    asm("{ .reg .u64 t; cvta.to.shared.u64 t, %1; cvt.u32.u64 %0, t; }"
        : "=r"(a) : "l"(p));
    return a;
}
__device__ __forceinline__ void cp_async16(uint32_t dst, const void* src) {
    asm volatile("cp.async.ca.shared.global [%0], [%1], 16;"
                 :: "r"(dst), "l"(src) : "memory");
}
#define CP_COMMIT() asm volatile("cp.async.commit_group;" ::: "memory")
#define CP_WAIT0()  asm volatile("cp.async.wait_group 0;" ::: "memory")

__device__ __forceinline__ void ldsm_x4(uint32_t* r, uint32_t addr) {
    asm volatile("ldmatrix.sync.aligned.m8n8.x4.shared.b16 {%0,%1,%2,%3}, [%4];"
                 : "=r"(r[0]), "=r"(r[1]), "=r"(r[2]), "=r"(r[3]) : "r"(addr));
}
__device__ __forceinline__ void ldsm_x4_t(uint32_t* r, uint32_t addr) {
    asm volatile("ldmatrix.sync.aligned.m8n8.x4.trans.shared.b16 {%0,%1,%2,%3}, [%4];"
                 : "=r"(r[0]), "=r"(r[1]), "=r"(r[2]), "=r"(r[3]) : "r"(addr));
}
__device__ __forceinline__ void mma_f16(float* d, const uint32_t* a,
                                        const uint32_t* b) {
    asm volatile(
        "mma.sync.aligned.m16n8k16.row.col.f32.f16.f16.f32 "
        "{%0,%1,%2,%3}, {%4,%5,%6,%7}, {%8,%9}, {%0,%1,%2,%3};"
        : "+f"(d[0]), "+f"(d[1]), "+f"(d[2]), "+f"(d[3])
        : "r"(a[0]), "r"(a[1]), "r"(a[2]), "r"(a[3]), "r"(b[0]), "r"(b[1]));
}

// ---------------------------------------------------------------------------
// Fused front kernel:
//   blocks [0, CVT_BLOCKS)                : v fp32 -> fp16 (8 elems/thread)
//   blocks [CVT_BLOCKS, +NH)              : z_pb scan per head (256 threads)
//   blocks [CVT_BLOCKS+NH, +5)            : zero pbv border rows j=0 / j=2047
// ---------------------------------------------------------------------------
__global__ __launch_bounds__(256) void front_kernel(const float* __restrict__ v,
                                                    const float* __restrict__ w,
                                                    float* __restrict__ outz,
                                                    float* __restrict__ out) {
    const int b = blockIdx.x;
    if (b < CVT_BLOCKS) {
        int i = (b * 256 + threadIdx.x) * 8;
        float4 x0 = *(const float4*)(v + i);
        float4 x1 = *(const float4*)(v + i + 4);
        __half2 h[4];
        h[0] = __floats2half2_rn(x0.x, x0.y);
        h[1] = __floats2half2_rn(x0.z, x0.w);
        h[2] = __floats2half2_rn(x1.x, x1.y);
        h[3] = __floats2half2_rn(x1.z, x1.w);
        *(uint4*)(vt_h + i) = *(uint4*)h;
        return;
    }
    if (b < CVT_BLOCKS + NH) {
        // ---- per-head prefix scan: z_pb[l,h] = P[l-1] + P[SEQ-l] - w[h,0]
        const int h = b - CVT_BLOCKS;
        __shared__ float buf[2][SS];
        const int t = threadIdx.x;
        for (int i = t; i < SS; i += 256)
            buf[0][i] = (i < SEQ) ? w[(size_t)h * SS + i] : 0.f;
        __syncthreads();
        int src = 0;
        for (int off = 1; off < SS; off <<= 1) {
            for (int i = t; i < SS; i += 256) {
                float val = buf[src][i];
                if (i >= off) val += buf[src][i - off];
                buf[src ^ 1][i] = val;
            }
            src ^= 1;
            __syncthreads();
        }
        const float w0 = buf[src][0];
        for (int l = t; l < SS; l += 256) {
            float zv = 0.f;
            if (l >= 1 && l <= SEQ)
                zv = buf[src][l - 1] + buf[src][SEQ - l] - w0;
            outz[(size_t)l * NH + h] = zv;
        }
        return;
    }
    // ---- border zeroing: 8 segments x 768 floats = 6144 elems
    {
        const int bb = b - CVT_BLOCKS - NH;       // 0..4
        for (int e = 0; e < 6; e++) {
            int gidx = (bb * 6 + e) * 256 + threadIdx.x;   // covers 5*1536=7680
            if (gidx < 8 * NH * ND) {
                int seg = gidx / (NH * ND);
                int off = gidx % (NH * ND);
                int n = seg >> 1;
                int j = (seg & 1) ? (SS - 1) : 0;
                out[((size_t)(n * SS + j) * NH * ND) + off] = 0.f;
            }
        }
    }
}

// ---------------------------------------------------------------------------
// pbv[n,j,h,d] = sum_l w[h,|l-j|] * v[n,l,h,d] as per-head Toeplitz GEMM.
// grid (32 j-tiles, 2 c-halves, 12 heads); CTA 64x128 fp16 MMA, 8 warps 32x32.
// Double-buffered, cp.async B, 3 CTAs/SM. (R9-proven core, untouched.)
// ---------------------------------------------------------------------------
__global__ __launch_bounds__(THREADS, 3) void pbv_mma(const float* __restrict__ w,
                                                      float* __restrict__ out) {
    __shared__ __half wsh[SS];                  // 4 KB fp16 w row
    extern __shared__ char dyn[];               // A0 | A1 | B0 | B1

    const int t    = threadIdx.x;
    const int wid  = t >> 5, lane = t & 31;
    const int g    = lane >> 2, t4 = lane & 3;
    const int wm   = wid >> 2;                  // 0..1 -> 32-row slab
    const int wn   = wid & 3;                   // 0..3 -> 32-col slab
    const int l15  = lane & 15, lhi = lane >> 4;

    const int jt = blockIdx.x, ch = blockIdx.y, h = blockIdx.z;
    const int j0 = jt * TM;
    const int c0 = ch * TN;

    {
        const float* wrow = w + (size_t)h * SS;
        for (int i = t; i < SS; i += THREADS) wsh[i] = __float2half_rn(wrow[i]);
    }
    __syncthreads();

    const __half* vtb = vt_h + h * ND;          // + (n*SS + l)*ROWSTRIDE + d
    const uint32_t sb = smem_u32(dyn);

    const int skp = t & 15;                     // half2 pair within k row
    const int sj  = t >> 4;                     // j row 0..15 (+16*i)

    auto stage = [&](int c) {
        const int k0 = c * KC;
        __half2* Ab = (__half2*)(dyn + (c & 1) * A_BYTES);
        const int l0 = k0 + 2 * skp;
        if (c != 0 && c != NCHUNK - 1) {        // fast path: all l valid
#pragma unroll
            for (int i = 0; i < 4; i++) {
                int jg = j0 + sj + 16 * i;
                int d0 = l0 - jg;     int a0i = d0 < 0 ? -d0 : d0;
                int d1 = d0 + 1;      int a1i = d1 < 0 ? -d1 : d1;
                Ab[(sj + 16 * i) * (A_STR / 2) + skp] =
                    __halves2half2(wsh[a0i], wsh[a1i]);
            }
        } else {                                 // edge chunks: l=0 / l=2047
#pragma unroll
            for (int i = 0; i < 4; i++) {
                int jg = j0 + sj + 16 * i;
                int d0 = l0 - jg;     int a0i = d0 < 0 ? -d0 : d0;
                int d1 = d0 + 1;      int a1i = d1 < 0 ? -d1 : d1;
                __half v0 = (l0 >= 1     && l0     <= SEQ) ? wsh[a0i] : __half(0.f);
                __half v1 = (l0 + 1 >= 1 && l0 + 1 <= SEQ) ? wsh[a1i] : __half(0.f);
                Ab[(sj + 16 * i) * (A_STR / 2) + skp] = __halves2half2(v0, v1);
            }
        }
        const uint32_t Bbase = sb + 2 * A_BYTES + (c & 1) * B_BYTES;
#pragma unroll
        for (int q = 0; q < 2; q++) {
            int fi = t + q * THREADS;           // 0..511, 16B slots
            int k  = fi >> 4, c8 = fi & 15;
            int cc = c0 + c8 * 8;
            int n  = cc >> 6, d = cc & 63;
            const __half* src = vtb + ((size_t)n * SS + (k0 + k)) * ROWSTRIDE + d;
            cp_async16(Bbase + (uint32_t)(k * B_STR + c8 * 8) * 2, src);
        }
        CP_COMMIT();
    };

    float acc[2][4][4];
#pragma unroll
    for (int mi = 0; mi < 2; mi++)
#pragma unroll
        for (int ni = 0; ni < 4; ni++)
#pragma unroll
            for (int r = 0; r < 4; r++) acc[mi][ni][r] = 0.f;

    const uint32_t aRow = (uint32_t)(wm * 32 + l15);       // + mi*16
    const uint32_t aKof = (uint32_t)(lhi * 8);             // + ks*16
    const uint32_t bRow = (uint32_t)l15;                   // + ks*16
    const uint32_t bCol = (uint32_t)(wn * 32 + lhi * 8);   // + ni2*16

    stage(0);

    for (int c = 0; c < NCHUNK; c++) {
        CP_WAIT0();
        __syncthreads();
        if (c + 1 < NCHUNK) stage(c + 1);

        const uint32_t Ao = sb + (c & 1) * A_BYTES;
        const uint32_t Bo = sb + 2 * A_BYTES + (c & 1) * B_BYTES;

#pragma unroll
        for (int ks = 0; ks < 2; ks++) {
            uint32_t a[2][4], b[4][2];
#pragma unroll
            for (int mi = 0; mi < 2; mi++)
                ldsm_x4(a[mi], Ao + ((aRow + mi * 16) * A_STR + aKof + ks * 16) * 2);
#pragma unroll
            for (int ni2 = 0; ni2 < 2; ni2++) {
                uint32_t r[4];
                ldsm_x4_t(r, Bo + ((bRow + ks * 16) * B_STR + bCol + ni2 * 16) * 2);
                b[2 * ni2][0] = r[0];      b[2 * ni2][1] = r[1];
                b[2 * ni2 + 1][0] = r[2];  b[2 * ni2 + 1][1] = r[3];
            }
#pragma unroll
            for (int mi = 0; mi < 2; mi++)
#pragma unroll
                for (int ni = 0; ni < 4; ni++)
                    mma_f16(acc[mi][ni], a[mi], b[ni]);
        }
    }

    // ---- epilogue: acc -> out[n, j, h, d]
#pragma unroll
    for (int mi = 0; mi < 2; mi++) {
        const int r0 = j0 + wm * 32 + mi * 16 + g;
#pragma unroll
        for (int ni = 0; ni < 4; ni++) {
            const int cc = c0 + wn * 32 + ni * 8 + 2 * t4;
            const int n = cc >> 6, d = cc & 63;
            float* o = out + (((size_t)n * SS) * NH + h) * ND + d;
            if (r0 >= 1 && r0 <= SEQ) {
                float2 s = make_float2(acc[mi][ni][0], acc[mi][ni][1]);
                *(float2*)(o + (size_t)r0 * NH * ND) = s;
            }
            const int r1 = r0 + 8;
            if (r1 >= 1 && r1 <= SEQ) {
                float2 s = make_float2(acc[mi][ni][2], acc[mi][ni][3]);
                *(float2*)(o + (size_t)r1 * NH * ND) = s;
            }
        }
    }
}

// ---------------------------------------------------------------------------
extern "C" void kernel_launch(void* const* d_in, const int* in_sizes, int n_in,
                              void* d_out, int out_size) {
    const float* a0 = (const float*)d_in[0];
    const float* a1 = (const float*)d_in[1];
    const float* v = a0;
    const float* w = a1;
    if (n_in >= 2 && in_sizes[0] < in_sizes[1]) { v = a1; w = a0; }

    float* out  = (float*)d_out;
    float* outz = out + (size_t)SB * SS * NH * ND;

    static int configured = 0;
    if (!configured) {
        cudaFuncSetAttribute(pbv_mma, cudaFuncAttributeMaxDynamicSharedMemorySize,
                             DYN_BYTES);
        configured = 1;
    }

    front_kernel<<<CVT_BLOCKS + ZB_BLOCKS, 256>>>(v, w, outz, out);
    dim3 grid(SS / TM, 256 / TN, NH);        // 32 x 2 x 12 = 768 CTAs
    pbv_mma<<<grid, THREADS, DYN_BYTES>>>(w, out);
}

// round 13
// speedup vs baseline: 2.0411x; 1.1456x over previous
#include <cuda_runtime.h>
#include <cuda_fp16.h>
#include <cstdint>

// ---------------- problem constants ----------------
#define SB   4
#define SS   2048
#define SEQ  2046
#define NH   12
#define ND   64
#define ROWSTRIDE (NH*ND)        // 768 elems between consecutive l in v
#define NV   (SB*SS*NH*ND)       // 6291456 elements of v

// ---------------- GEMM tiling ----------------
#define TM    64                 // j rows per CTA
#define TN    128                // c cols per CTA
#define KC    32                 // l per chunk
#define NCHUNK (SS / KC)         // 64
#define THREADS 256

#define B_STR  136               // halves per k row (128 c + 8 pad)
#define B_BYTES (KC * B_STR * 2)          // 8704
#define T_BYTES 16384                     // 4095 half2 pairs, padded
#define DYN_BYTES (T_BYTES + 2*B_BYTES)   // 33792

// fused front kernel grid split
#define CVT_BLOCKS 3072          // 3072 * 256 * 8 = NV
#define ZB_BLOCKS  17            // 12 scan + 5 border

// fp16 copy of v, rows l=0 / l=2047 zeroed (device-global scratch)
__device__ __half vt_h[NV];

__device__ __forceinline__ uint32_t smem_u32(const void* p) {
    uint32_t a;
    asm("{ .reg .u64 t; cvta.to.shared.u64 t, %1; cvt.u32.u64 %0, t; }"
        : "=r"(a) : "l"(p));
    return a;
}
__device__ __forceinline__ void cp_async16(uint32_t dst, const void* src) {
    asm volatile("cp.async.ca.shared.global [%0], [%1], 16;"
                 :: "r"(dst), "l"(src) : "memory");
}
#define CP_COMMIT() asm volatile("cp.async.commit_group;" ::: "memory")
#define CP_WAIT0()  asm volatile("cp.async.wait_group 0;" ::: "memory")

__device__ __forceinline__ uint32_t lds32(uint32_t addr) {
    uint32_t v;
    asm("ld.shared.b32 %0, [%1];" : "=r"(v) : "r"(addr));
    return v;
}
__device__ __forceinline__ void ldsm_x4_t(uint32_t* r, uint32_t addr) {
    asm volatile("ldmatrix.sync.aligned.m8n8.x4.trans.shared.b16 {%0,%1,%2,%3}, [%4];"
                 : "=r"(r[0]), "=r"(r[1]), "=r"(r[2]), "=r"(r[3]) : "r"(addr));
}
__device__ __forceinline__ void mma_f16(float* d, const uint32_t* a,
                                        const uint32_t* b) {
    asm volatile(
        "mma.sync.aligned.m16n8k16.row.col.f32.f16.f16.f32 "
        "{%0,%1,%2,%3}, {%4,%5,%6,%7}, {%8,%9}, {%0,%1,%2,%3};"
        : "+f"(d[0]), "+f"(d[1]), "+f"(d[2]), "+f"(d[3])
        : "r"(a[0]), "r"(a[1]), "r"(a[2]), "r"(a[3]), "r"(b[0]), "r"(b[1]));
}

// ---------------------------------------------------------------------------
// Fused front kernel:
//   blocks [0, CVT_BLOCKS)     : v fp32 -> fp16 (8/thread); rows l=0,2047 -> 0
//   blocks [CVT_BLOCKS, +NH)   : z_pb scan per head
//   blocks [CVT_BLOCKS+NH, +5) : zero pbv border rows j=0 / j=2047
// ---------------------------------------------------------------------------
__global__ __launch_bounds__(256) void front_kernel(const float* __restrict__ v,
                                                    const float* __restrict__ w,
                                                    float* __restrict__ outz,
                                                    float* __restrict__ out) {
    const int b = blockIdx.x;
    if (b < CVT_BLOCKS) {
        int i = (b * 256 + threadIdx.x) * 8;
        int l = (i / ROWSTRIDE) & (SS - 1);         // all 8 elems share l
        if (l == 0 || l == SS - 1) {
            uint4 z = make_uint4(0, 0, 0, 0);       // invalid l rows -> 0
            *(uint4*)(vt_h + i) = z;
            return;
        }
        float4 x0 = *(const float4*)(v + i);
        float4 x1 = *(const float4*)(v + i + 4);
        __half2 h[4];
        h[0] = __floats2half2_rn(x0.x, x0.y);
        h[1] = __floats2half2_rn(x0.z, x0.w);
        h[2] = __floats2half2_rn(x1.x, x1.y);
        h[3] = __floats2half2_rn(x1.z, x1.w);
        *(uint4*)(vt_h + i) = *(uint4*)h;
        return;
    }
    if (b < CVT_BLOCKS + NH) {
        const int h = b - CVT_BLOCKS;
        __shared__ float buf[2][SS];
        const int t = threadIdx.x;
        for (int i = t; i < SS; i += 256)
            buf[0][i] = (i < SEQ) ? w[(size_t)h * SS + i] : 0.f;
        __syncthreads();
        int src = 0;
        for (int off = 1; off < SS; off <<= 1) {
            for (int i = t; i < SS; i += 256) {
                float val = buf[src][i];
                if (i >= off) val += buf[src][i - off];
                buf[src ^ 1][i] = val;
            }
            src ^= 1;
            __syncthreads();
        }
        const float w0 = buf[src][0];
        for (int l = t; l < SS; l += 256) {
            float zv = 0.f;
            if (l >= 1 && l <= SEQ)
                zv = buf[src][l - 1] + buf[src][SEQ - l] - w0;
            outz[(size_t)l * NH + h] = zv;
        }
        return;
    }
    {   // border zeroing: 8 segments x 768 floats
        const int bb = b - CVT_BLOCKS - NH;
        for (int e = 0; e < 6; e++) {
            int gidx = (bb * 6 + e) * 256 + threadIdx.x;
            if (gidx < 8 * NH * ND) {
                int seg = gidx / (NH * ND);
                int off = gidx % (NH * ND);
                int n = seg >> 1;
                int j = (seg & 1) ? (SS - 1) : 0;
                out[((size_t)(n * SS + j) * NH * ND) + off] = 0.f;
            }
        }
    }
}

// ---------------------------------------------------------------------------
// pbv as per-head Toeplitz GEMM, A fragments loaded DIRECTLY from a
// difference-indexed table T[d] = (w[|d|], w[|d+1|]) -- no A tile in smem.
// grid (32 j-tiles, 2 c-halves, 12 heads); CTA 64x128, 8 warps 32x32.
// ---------------------------------------------------------------------------
__global__ __launch_bounds__(THREADS, 3) void pbv_mma(const float* __restrict__ w,
                                                      float* __restrict__ out) {
    __shared__ __half wsh[SS];                  // 4 KB fp16 w row
    extern __shared__ char dyn[];               // T | B0 | B1

    const int t    = threadIdx.x;
    const int wid  = t >> 5, lane = t & 31;
    const int g    = lane >> 2, t4 = lane & 3;
    const int wm   = wid >> 2;                  // 0..1 -> 32-row slab
    const int wn   = wid & 3;                   // 0..3 -> 32-col slab
    const int l15  = lane & 15, lhi = lane >> 4;

    const int jt = blockIdx.x, ch = blockIdx.y, h = blockIdx.z;
    const int j0 = jt * TM;
    const int c0 = ch * TN;

    const uint32_t sb = smem_u32(dyn);

    {   // stage w row as fp16
        const float* wrow = w + (size_t)h * SS;
        for (int i = t; i < SS; i += THREADS) wsh[i] = __float2half_rn(wrow[i]);
    }
    __syncthreads();

    {   // build T[d] = (w[|d|], w[|d+1|]) for d in [-2047, 2047]
        __half2* T = (__half2*)dyn;
        for (int i = t; i < 4095; i += THREADS) {
            int d  = i - 2047;
            int a0 = d < 0 ? -d : d;
            int d1 = d + 1;
            int a1 = d1 < 0 ? -d1 : d1;
            T[i] = __halves2half2(wsh[a0], wsh[a1]);
        }
    }
    __syncthreads();

    const __half* vtb = vt_h + h * ND;          // + (n*SS + l)*ROWSTRIDE + d

    // per-lane A pointer into T, centered: d = c*KC + 2*t4 - j0 - wm*32 - g
    uint32_t aP = sb + 2047u * 4 +
                  (uint32_t)(4 * (2 * t4 - j0 - wm * 32 - g));

    auto stageB = [&](int c) {
        const int k0 = c * KC;
        const uint32_t Bbase = sb + T_BYTES + (c & 1) * B_BYTES;
#pragma unroll
        for (int q = 0; q < 2; q++) {
            int fi = t + q * THREADS;           // 0..511, 16B slots
            int k  = fi >> 4, c8 = fi & 15;
            int cc = c0 + c8 * 8;
            int n  = cc >> 6, d = cc & 63;
            const __half* src = vtb + ((size_t)n * SS + (k0 + k)) * ROWSTRIDE + d;
            cp_async16(Bbase + (uint32_t)(k * B_STR + c8 * 8) * 2, src);
        }
        CP_COMMIT();
    };

    float acc[2][4][4];
#pragma unroll
    for (int mi = 0; mi < 2; mi++)
#pragma unroll
        for (int ni = 0; ni < 4; ni++)
#pragma unroll
            for (int r = 0; r < 4; r++) acc[mi][ni][r] = 0.f;

    const uint32_t bRow = (uint32_t)l15;                   // + ks*16
    const uint32_t bCol = (uint32_t)(wn * 32 + lhi * 8);   // + ni2*16

    stageB(0);

    for (int c = 0; c < NCHUNK; c++) {
        CP_WAIT0();
        __syncthreads();
        if (c + 1 < NCHUNK) stageB(c + 1);

        // 7 A loads cover ALL fragment registers of this chunk (Toeplitz reuse)
        uint32_t A7[7];
#pragma unroll
        for (int o = 0; o < 7; o++)
            A7[o] = lds32(aP + (uint32_t)(o * 32) - 96u);

        const uint32_t Bo = sb + T_BYTES + (c & 1) * B_BYTES;

#pragma unroll
        for (int ks = 0; ks < 2; ks++) {
            uint32_t b[4][2];
#pragma unroll
            for (int ni2 = 0; ni2 < 2; ni2++) {
                uint32_t r[4];
                ldsm_x4_t(r, Bo + ((bRow + ks * 16) * B_STR + bCol + ni2 * 16) * 2);
                b[2 * ni2][0] = r[0];      b[2 * ni2][1] = r[1];
                b[2 * ni2 + 1][0] = r[2];  b[2 * ni2 + 1][1] = r[3];
            }
#pragma unroll
            for (int mi = 0; mi < 2; mi++) {
                const int i0 = 3 + 2 * ks - 2 * mi;        // 1..5
                uint32_t a[4] = { A7[i0], A7[i0 - 1], A7[i0 + 1], A7[i0] };
#pragma unroll
                for (int ni = 0; ni < 4; ni++)
                    mma_f16(acc[mi][ni], a, b[ni]);
            }
        }
        aP += KC * 4;                            // advance d by KC
    }

    // ---- epilogue: acc -> out[n, j, h, d]
#pragma unroll
    for (int mi = 0; mi < 2; mi++) {
        const int r0 = j0 + wm * 32 + mi * 16 + g;
#pragma unroll
        for (int ni = 0; ni < 4; ni++) {
            const int cc = c0 + wn * 32 + ni * 8 + 2 * t4;
            const int n = cc >> 6, d = cc & 63;
            float* o = out + (((size_t)n * SS) * NH + h) * ND + d;
            if (r0 >= 1 && r0 <= SEQ) {
                float2 s = make_float2(acc[mi][ni][0], acc[mi][ni][1]);
                *(float2*)(o + (size_t)r0 * NH * ND) = s;
            }
            const int r1 = r0 + 8;
            if (r1 >= 1 && r1 <= SEQ) {
                float2 s = make_float2(acc[mi][ni][2], acc[mi][ni][3]);
                *(float2*)(o + (size_t)r1 * NH * ND) = s;
            }
        }
    }
}

// ---------------------------------------------------------------------------
extern "C" void kernel_launch(void* const* d_in, const int* in_sizes, int n_in,
                              void* d_out, int out_size) {
    const float* a0 = (const float*)d_in[0];
    const float* a1 = (const float*)d_in[1];
    const float* v = a0;
    const float* w = a1;
    if (n_in >= 2 && in_sizes[0] < in_sizes[1]) { v = a1; w = a0; }

    float* out  = (float*)d_out;
    float* outz = out + (size_t)SB * SS * NH * ND;

    static int configured = 0;
    if (!configured) {
        cudaFuncSetAttribute(pbv_mma, cudaFuncAttributeMaxDynamicSharedMemorySize,
                             DYN_BYTES);
        configured = 1;
    }

    front_kernel<<<CVT_BLOCKS + ZB_BLOCKS, 256>>>(v, w, outz, out);
    dim3 grid(SS / TM, 256 / TN, NH);        // 32 x 2 x 12 = 768 CTAs
    pbv_mma<<<grid, THREADS, DYN_BYTES>>>(w, out);
}

// round 14
// speedup vs baseline: 2.2349x; 1.0949x over previous
#include <cuda_runtime.h>
#include <cuda_fp16.h>
#include <cstdint>

// ---------------- problem constants ----------------
#define SB   4
#define SS   2048
#define SEQ  2046
#define NH   12
#define ND   64
#define ROWSTRIDE (NH*ND)        // 768 elems between consecutive l in v
#define NV   (SB*SS*NH*ND)       // 6291456 elements of v

// ---------------- GEMM tiling ----------------
#define TM    64                 // j rows per CTA
#define TN    128                // c cols per CTA
#define KC    64                 // l per chunk (doubled: A-staging is free now)
#define NCHUNK (SS / KC)         // 32
#define THREADS 256

#define B_STR  136               // halves per k row (128 c + 8 pad)
#define B_BYTES (KC * B_STR * 2)          // 17408
#define T_BYTES 16384                     // 4095 half2 pairs, padded
#define DYN_BYTES (T_BYTES + 2*B_BYTES)   // 51200

// fused front kernel grid split
#define CVT_BLOCKS 3072          // 3072 * 256 * 8 = NV
#define ZB_BLOCKS  17            // 12 scan + 5 border

// fp16 copy of v, rows l=0 / l=2047 zeroed (device-global scratch)
__device__ __half vt_h[NV];

__device__ __forceinline__ uint32_t smem_u32(const void* p) {
    uint32_t a;
    asm("{ .reg .u64 t; cvta.to.shared.u64 t, %1; cvt.u32.u64 %0, t; }"
        : "=r"(a) : "l"(p));
    return a;
}
__device__ __forceinline__ void cp_async16(uint32_t dst, const void* src) {
    asm volatile("cp.async.ca.shared.global [%0], [%1], 16;"
                 :: "r"(dst), "l"(src) : "memory");
}
#define CP_COMMIT() asm volatile("cp.async.commit_group;" ::: "memory")
#define CP_WAIT0()  asm volatile("cp.async.wait_group 0;" ::: "memory")

__device__ __forceinline__ uint32_t lds32(uint32_t addr) {
    uint32_t v;
    asm("ld.shared.b32 %0, [%1];" : "=r"(v) : "r"(addr));
    return v;
}
__device__ __forceinline__ void ldsm_x4_t(uint32_t* r, uint32_t addr) {
    asm volatile("ldmatrix.sync.aligned.m8n8.x4.trans.shared.b16 {%0,%1,%2,%3}, [%4];"
                 : "=r"(r[0]), "=r"(r[1]), "=r"(r[2]), "=r"(r[3]) : "r"(addr));
}
__device__ __forceinline__ void mma_f16(float* d, const uint32_t* a,
                                        const uint32_t* b) {
    asm volatile(
        "mma.sync.aligned.m16n8k16.row.col.f32.f16.f16.f32 "
        "{%0,%1,%2,%3}, {%4,%5,%6,%7}, {%8,%9}, {%0,%1,%2,%3};"
        : "+f"(d[0]), "+f"(d[1]), "+f"(d[2]), "+f"(d[3])
        : "r"(a[0]), "r"(a[1]), "r"(a[2]), "r"(a[3]), "r"(b[0]), "r"(b[1]));
}

// ---------------------------------------------------------------------------
// Fused front kernel:
//   blocks [0, CVT_BLOCKS)     : v fp32 -> fp16 (8/thread); rows l=0,2047 -> 0
//   blocks [CVT_BLOCKS, +NH)   : z_pb scan per head
//   blocks [CVT_BLOCKS+NH, +5) : zero pbv border rows j=0 / j=2047
// ---------------------------------------------------------------------------
__global__ __launch_bounds__(256) void front_kernel(const float* __restrict__ v,
                                                    const float* __restrict__ w,
                                                    float* __restrict__ outz,
                                                    float* __restrict__ out) {
    const int b = blockIdx.x;
    if (b < CVT_BLOCKS) {
        int i = (b * 256 + threadIdx.x) * 8;
        int l = (i / ROWSTRIDE) & (SS - 1);         // all 8 elems share l
        if (l == 0 || l == SS - 1) {
            uint4 z = make_uint4(0, 0, 0, 0);       // invalid l rows -> 0
            *(uint4*)(vt_h + i) = z;
            return;
        }
        float4 x0 = *(const float4*)(v + i);
        float4 x1 = *(const float4*)(v + i + 4);
        __half2 h[4];
        h[0] = __floats2half2_rn(x0.x, x0.y);
        h[1] = __floats2half2_rn(x0.z, x0.w);
        h[2] = __floats2half2_rn(x1.x, x1.y);
        h[3] = __floats2half2_rn(x1.z, x1.w);
        *(uint4*)(vt_h + i) = *(uint4*)h;
        return;
    }
    if (b < CVT_BLOCKS + NH) {
        const int h = b - CVT_BLOCKS;
        __shared__ float buf[2][SS];
        const int t = threadIdx.x;
        for (int i = t; i < SS; i += 256)
            buf[0][i] = (i < SEQ) ? w[(size_t)h * SS + i] : 0.f;
        __syncthreads();
        int src = 0;
        for (int off = 1; off < SS; off <<= 1) {
            for (int i = t; i < SS; i += 256) {
                float val = buf[src][i];
                if (i >= off) val += buf[src][i - off];
                buf[src ^ 1][i] = val;
            }
            src ^= 1;
            __syncthreads();
        }
        const float w0 = buf[src][0];
        for (int l = t; l < SS; l += 256) {
            float zv = 0.f;
            if (l >= 1 && l <= SEQ)
                zv = buf[src][l - 1] + buf[src][SEQ - l] - w0;
            outz[(size_t)l * NH + h] = zv;
        }
        return;
    }
    {   // border zeroing: 8 segments x 768 floats
        const int bb = b - CVT_BLOCKS - NH;
        for (int e = 0; e < 6; e++) {
            int gidx = (bb * 6 + e) * 256 + threadIdx.x;
            if (gidx < 8 * NH * ND) {
                int seg = gidx / (NH * ND);
                int off = gidx % (NH * ND);
                int n = seg >> 1;
                int j = (seg & 1) ? (SS - 1) : 0;
                out[((size_t)(n * SS + j) * NH * ND) + off] = 0.f;
            }
        }
    }
}

// ---------------------------------------------------------------------------
// pbv as per-head Toeplitz GEMM, A fragments from difference-indexed table
// T[d] = (w[|d|], w[|d+1|]); no A tile. KC=64 halves the sync cadence.
// grid (32 j-tiles, 2 c-halves, 12 heads); CTA 64x128, 8 warps 32x32.
// ---------------------------------------------------------------------------
__global__ __launch_bounds__(THREADS, 3) void pbv_mma(const float* __restrict__ w,
                                                      float* __restrict__ out) {
    __shared__ __half wsh[SS];                  // 4 KB fp16 w row
    extern __shared__ char dyn[];               // T | B0 | B1

    const int t    = threadIdx.x;
    const int wid  = t >> 5, lane = t & 31;
    const int g    = lane >> 2, t4 = lane & 3;
    const int wm   = wid >> 2;                  // 0..1 -> 32-row slab
    const int wn   = wid & 3;                   // 0..3 -> 32-col slab
    const int l15  = lane & 15, lhi = lane >> 4;

    const int jt = blockIdx.x, ch = blockIdx.y, h = blockIdx.z;
    const int j0 = jt * TM;
    const int c0 = ch * TN;

    const uint32_t sb = smem_u32(dyn);

    {   // stage w row as fp16
        const float* wrow = w + (size_t)h * SS;
        for (int i = t; i < SS; i += THREADS) wsh[i] = __float2half_rn(wrow[i]);
    }
    __syncthreads();

    {   // build T[d] = (w[|d|], w[|d+1|]) for d in [-2047, 2047]
        __half2* T = (__half2*)dyn;
        for (int i = t; i < 4095; i += THREADS) {
            int d  = i - 2047;
            int a0 = d < 0 ? -d : d;
            int d1 = d + 1;
            int a1 = d1 < 0 ? -d1 : d1;
            T[i] = __halves2half2(wsh[a0], wsh[a1]);
        }
    }
    __syncthreads();

    const __half* vtb = vt_h + h * ND;          // + (n*SS + l)*ROWSTRIDE + d

    // per-lane A pointer into T: word index = 2047 + 2*t4 - j0 - wm*32 - g (+d)
    uint32_t aP = sb + 2047u * 4 +
                  (uint32_t)(4 * (2 * t4 - j0 - wm * 32 - g));

    auto stageB = [&](int c) {
        const int k0 = c * KC;
        const uint32_t Bbase = sb + T_BYTES + (c & 1) * B_BYTES;
#pragma unroll
        for (int q = 0; q < 4; q++) {
            int fi = t + q * THREADS;           // 0..1023, 16B slots
            int k  = fi >> 4, c8 = fi & 15;     // 64 rows x 16 slots
            int cc = c0 + c8 * 8;
            int n  = cc >> 6, d = cc & 63;
            const __half* src = vtb + ((size_t)n * SS + (k0 + k)) * ROWSTRIDE + d;
            cp_async16(Bbase + (uint32_t)(k * B_STR + c8 * 8) * 2, src);
        }
        CP_COMMIT();
    };

    float acc[2][4][4];
#pragma unroll
    for (int mi = 0; mi < 2; mi++)
#pragma unroll
        for (int ni = 0; ni < 4; ni++)
#pragma unroll
            for (int r = 0; r < 4; r++) acc[mi][ni][r] = 0.f;

    const uint32_t bRow = (uint32_t)l15;                   // + ks*16
    const uint32_t bCol = (uint32_t)(wn * 32 + lhi * 8);   // + ni2*16

    stageB(0);

    for (int c = 0; c < NCHUNK; c++) {
        CP_WAIT0();
        __syncthreads();
        if (c + 1 < NCHUNK) stageB(c + 1);

        // 11 A loads cover all fragments for ks=0..3, mi=0..1 (Toeplitz reuse)
        uint32_t A11[11];
#pragma unroll
        for (int o = 0; o < 11; o++)
            A11[o] = lds32(aP + (uint32_t)(o * 32) - 96u);

        const uint32_t Bo = sb + T_BYTES + (c & 1) * B_BYTES;

#pragma unroll
        for (int ks = 0; ks < 4; ks++) {
            uint32_t b[4][2];
#pragma unroll
            for (int ni2 = 0; ni2 < 2; ni2++) {
                uint32_t r[4];
                ldsm_x4_t(r, Bo + ((bRow + ks * 16) * B_STR + bCol + ni2 * 16) * 2);
                b[2 * ni2][0] = r[0];      b[2 * ni2][1] = r[1];
                b[2 * ni2 + 1][0] = r[2];  b[2 * ni2 + 1][1] = r[3];
            }
#pragma unroll
            for (int mi = 0; mi < 2; mi++) {
                const int i0 = 3 + 2 * ks - 2 * mi;        // 1..9
                uint32_t a[4] = { A11[i0], A11[i0 - 1], A11[i0 + 1], A11[i0] };
#pragma unroll
                for (int ni = 0; ni < 4; ni++)
                    mma_f16(acc[mi][ni], a, b[ni]);
            }
        }
        aP += KC * 4;                            // advance d by KC
    }

    // ---- epilogue: acc -> out[n, j, h, d]
#pragma unroll
    for (int mi = 0; mi < 2; mi++) {
        const int r0 = j0 + wm * 32 + mi * 16 + g;
#pragma unroll
        for (int ni = 0; ni < 4; ni++) {
            const int cc = c0 + wn * 32 + ni * 8 + 2 * t4;
            const int n = cc >> 6, d = cc & 63;
            float* o = out + (((size_t)n * SS) * NH + h) * ND + d;
            if (r0 >= 1 && r0 <= SEQ) {
                float2 s = make_float2(acc[mi][ni][0], acc[mi][ni][1]);
                *(float2*)(o + (size_t)r0 * NH * ND) = s;
            }
            const int r1 = r0 + 8;
            if (r1 >= 1 && r1 <= SEQ) {
                float2 s = make_float2(acc[mi][ni][2], acc[mi][ni][3]);
                *(float2*)(o + (size_t)r1 * NH * ND) = s;
            }
        }
    }
}

// ---------------------------------------------------------------------------
extern "C" void kernel_launch(void* const* d_in, const int* in_sizes, int n_in,
                              void* d_out, int out_size) {
    const float* a0 = (const float*)d_in[0];
    const float* a1 = (const float*)d_in[1];
    const float* v = a0;
    const float* w = a1;
    if (n_in >= 2 && in_sizes[0] < in_sizes[1]) { v = a1; w = a0; }

    float* out  = (float*)d_out;
    float* outz = out + (size_t)SB * SS * NH * ND;

    static int configured = 0;
    if (!configured) {
        cudaFuncSetAttribute(pbv_mma, cudaFuncAttributeMaxDynamicSharedMemorySize,
                             DYN_BYTES);
        configured = 1;
    }

    front_kernel<<<CVT_BLOCKS + ZB_BLOCKS, 256>>>(v, w, outz, out);
    dim3 grid(SS / TM, 256 / TN, NH);        // 32 x 2 x 12 = 768 CTAs
    pbv_mma<<<grid, THREADS, DYN_BYTES>>>(w, out);
}